// round 7
// baseline (speedup 1.0000x reference)
#include <cuda_runtime.h>
#include <cuda_bf16.h>
#include <cuda_fp16.h>

#define N_POINTS    262144
#define NUM_CLASSES 20
#define K_NEIGHBORS 16
#define FULLMASK    0xffffffffu

// packed labels: 5 bits each, 6 per uint32
#define NWORDS      43691            // ceil(262144 / 6)
#define NWORDS_PAD  43692            // multiple of 4 for uint4 copies

#define GRID2       152
#define TPB2        1024
#define NWARPS      (TPB2 / 32)
#define QCAP        160              // per-warp match queue entries (31 + 128 worst case)
#define SMEM_BYTES  (NWORDS_PAD * 4 + NWARPS * QCAP * 8)   // 174768 + 40960 = 215728

#define N_TASKS     (N_POINTS * 4)   // (point, quarter) tasks, 4 neighbors each

// probs as fp16: 3 transposed uint4 planes (8 halves = 8 classes per plane; 20..23 zero)
__device__ uint4 g_probsh[3 * N_POINTS];
__device__ unsigned g_packed[NWORDS_PAD];
__device__ double g_sum;
__device__ unsigned long long g_count;
__device__ unsigned int g_done;

// ---------------------------------------------------------------------------
// Index-dtype detection (values lie in [0,N); int32 read as int64 -> OOB).
// ---------------------------------------------------------------------------
__device__ __forceinline__ bool detect_is64(const void* __restrict__ ref_raw) {
    __shared__ int s_is64;
    if (threadIdx.x < 32) {
        const long long* p = (const long long*)ref_raw;
        long long a = p[threadIdx.x];
        long long b = p[threadIdx.x + 32];
        int bad = (a < 0 || a >= (long long)N_POINTS ||
                   b < 0 || b >= (long long)N_POINTS) ? 1 : 0;
        unsigned m = __ballot_sync(FULLMASK, bad);
        if (threadIdx.x == 0) s_is64 = (m == 0u);
    }
    __syncthreads();
    return s_is64 != 0;
}

// label extract from packed table: q = i/6 via reciprocal, r = i%6
__device__ __forceinline__ int lab_extract(const unsigned* __restrict__ tab, int i) {
    unsigned q = __umulhi((unsigned)i, 715827883u);   // floor(i/6) exact for i<2^18
    unsigned r = (unsigned)i - q * 6u;
    return (int)((tab[q] >> (r * 5u)) & 31u);
}

// load one task's 4 neighbor indices (coalesced, both dtype layouts)
__device__ __forceinline__ void load_idx4(const void* __restrict__ ref_raw,
                                          bool is64, int i, int q, int* idxv) {
    if (is64) {
        const int4* base = (const int4*)((const char*)ref_raw +
                            (size_t)i * 128 + (size_t)q * 32);
        int4 v0 = base[0];
        int4 v1 = base[1];
        idxv[0] = v0.x; idxv[1] = v0.z;   // low words; -1 preserved
        idxv[2] = v1.x; idxv[3] = v1.z;
    } else {
        const int4* base = (const int4*)((const char*)ref_raw +
                            (size_t)i * 64 + (size_t)q * 16);
        int4 v0 = base[0];
        idxv[0] = v0.x; idxv[1] = v0.y; idxv[2] = v0.z; idxv[3] = v0.w;
    }
}

// squared distance over 20 probs (fp16 storage, fp32 math)
__device__ __forceinline__ float comp8(unsigned ua, unsigned ub, float d) {
    float2 fa = __half22float2(*(const __half2*)&ua);
    float2 fb = __half22float2(*(const __half2*)&ub);
    float d0 = fa.x - fb.x;
    float d1 = fa.y - fb.y;
    d = fmaf(d0, d0, d);
    return fmaf(d1, d1, d);
}

__device__ __forceinline__ float dist20(int a, int b) {
    float d = 0.f;
#pragma unroll
    for (int j = 0; j < 3; j++) {
        uint4 pa = g_probsh[j * N_POINTS + a];
        uint4 pb = g_probsh[j * N_POINTS + b];
        d = comp8(pa.x, pb.x, d);
        d = comp8(pa.y, pb.y, d);
        d = comp8(pa.z, pb.z, d);
        d = comp8(pa.w, pb.w, d);
    }
    return d;
}

// ---------------------------------------------------------------------------
// Pass 1: zero accumulators, pack labels (5-bit), row softmax -> fp16 planes.
// ---------------------------------------------------------------------------
__global__ void lac_pass1(const float* __restrict__ logits,
                          const void* __restrict__ labels_raw,
                          const void* __restrict__ ref_raw) {
    const bool is64 = detect_is64(ref_raw);
    int i = blockIdx.x * blockDim.x + threadIdx.x;
    if (blockIdx.x == 0 && threadIdx.x == 0) { g_sum = 0.0; g_count = 0ULL; }

    if (i < NWORDS_PAD) {
        unsigned w = 0;
#pragma unroll
        for (int t = 0; t < 6; t++) {
            int p = i * 6 + t;
            int lbl = 31;   // invalid sentinel
            if (p < N_POINTS) {
                long long v = is64 ? ((const long long*)labels_raw)[p]
                                   : (long long)((const int*)labels_raw)[p];
                lbl = (int)v & 31;   // -1 -> 31 (invalid); 0..19 preserved
            }
            w |= (unsigned)lbl << (t * 5);
        }
        g_packed[i] = w;
    }

    if (i >= N_POINTS) return;

    const float4* in = (const float4*)logits + (long long)i * 5;
    float4 v[5];
#pragma unroll
    for (int j = 0; j < 5; j++) v[j] = in[j];
    float* f = (float*)v;

    float m = f[0];
#pragma unroll
    for (int j = 1; j < NUM_CLASSES; j++) m = fmaxf(m, f[j]);
    float s = 0.f;
#pragma unroll
    for (int j = 0; j < NUM_CLASSES; j++) { float e = __expf(f[j] - m); f[j] = e; s += e; }
    float inv = __frcp_rn(s);
#pragma unroll
    for (int j = 0; j < NUM_CLASSES; j++) f[j] *= inv;

    // pack to 10 half2 + 2 zero half2, store as 3 uint4 planes (transposed)
    unsigned h[12];
#pragma unroll
    for (int c = 0; c < 10; c++) {
        __half2 hh = __floats2half2_rn(f[2 * c], f[2 * c + 1]);
        h[c] = *(unsigned*)&hh;
    }
    h[10] = 0u; h[11] = 0u;
#pragma unroll
    for (int j = 0; j < 3; j++) {
        uint4 P;
        P.x = h[j * 4 + 0]; P.y = h[j * 4 + 1];
        P.z = h[j * 4 + 2]; P.w = h[j * 4 + 3];
        g_probsh[j * N_POINTS + i] = P;
    }
}

// ---------------------------------------------------------------------------
// Pass 2: persistent blocks; smem label table; warp-aggregated match queue ->
// dense 32-lane distance batches; block reduce; last-block finalize.
// ---------------------------------------------------------------------------
__global__ void __launch_bounds__(TPB2, 1)
lac_pass2(const void* __restrict__ ref_raw, float* __restrict__ out) {
    extern __shared__ unsigned s_lab[];
    int2* s_q = (int2*)(s_lab + NWORDS_PAD);
    const bool is64 = detect_is64(ref_raw);

    {
        const uint4* src = (const uint4*)g_packed;
        uint4* dst = (uint4*)s_lab;
        for (int t = threadIdx.x; t < NWORDS_PAD / 4; t += blockDim.x)
            dst[t] = src[t];
    }
    __syncthreads();

    const int lane = threadIdx.x & 31;
    const int wid  = threadIdx.x >> 5;
    const int woff = wid * QCAP;

    float acc = 0.f;
    int   cnt = 0;
    int   qsize = 0;

    const int stride = GRID2 * TPB2;
    // N_TASKS divisible by 32 and thread ids warp-contiguous -> warp-uniform trip count
    for (int task = blockIdx.x * TPB2 + threadIdx.x; task < N_TASKS; task += stride) {
        int i = task >> 2;          // point
        int q = task & 3;           // 4-neighbor quarter

        int idxv[4];
        load_idx4(ref_raw, is64, i, q, idxv);

        int myl = lab_extract(s_lab, i);

        unsigned mask = 0;
#pragma unroll
        for (int k = 0; k < 4; k++) {
            int safe = max(idxv[k], 0);
            int nl = lab_extract(s_lab, safe);
            if (idxv[k] >= 0 && nl == myl && myl != 31) mask |= 1u << k;
        }

        // warp-scan of per-lane match counts -> append offsets
        int n = __popc(mask);
        int scan = n;
#pragma unroll
        for (int o = 1; o < 32; o <<= 1) {
            int v = __shfl_up_sync(FULLMASK, scan, o);
            if (lane >= o) scan += v;
        }
        int total = __shfl_sync(FULLMASK, scan, 31);
        int off = qsize + scan - n;

        unsigned mm = mask;
        while (mm) {
            int k = __ffs(mm) - 1;
            mm &= mm - 1;
            s_q[woff + off] = make_int2(i, idxv[k]);
            off++;
        }
        cnt += n;
        qsize += total;

        // drain full batches: 32 lanes, one match each (dense gathers)
        int h = 0;
        while (qsize >= 32) {
            int2 e = s_q[woff + h + lane];
            acc += dist20(e.x, e.y);
            h += 32;
            qsize -= 32;
        }
        // compact leftover to the front (disjoint regions: h>=32 > qsize)
        if (h && qsize) {
            int2 e;
            if (lane < qsize) e = s_q[woff + h + lane];
            if (lane < qsize) s_q[woff + lane] = e;
        }
    }

    // tail: drain remaining (<32) entries
    if (lane < qsize) {
        int2 e = s_q[woff + lane];
        acc += dist20(e.x, e.y);
    }

    // block reduction (32 warps) -> one atomic per block -> last-block finalize
#pragma unroll
    for (int o = 16; o > 0; o >>= 1) {
        acc += __shfl_down_sync(FULLMASK, acc, o);
        cnt += __shfl_down_sync(FULLMASK, cnt, o);
    }
    __shared__ float ssum[32];
    __shared__ int   scnt[32];
    if (lane == 0) { ssum[wid] = acc; scnt[wid] = cnt; }
    __syncthreads();
    if (wid == 0) {
        acc = ssum[lane];
        cnt = scnt[lane];
#pragma unroll
        for (int o = 16; o > 0; o >>= 1) {
            acc += __shfl_down_sync(FULLMASK, acc, o);
            cnt += __shfl_down_sync(FULLMASK, cnt, o);
        }
        if (lane == 0) {
            atomicAdd(&g_sum, (double)acc);
            atomicAdd(&g_count, (unsigned long long)cnt);
            __threadfence();
            unsigned int done = atomicAdd(&g_done, 1u);
            if (done == gridDim.x - 1) {
                double sum = *(volatile double*)&g_sum;
                double c   = (double)*(volatile unsigned long long*)&g_count;
                if (c < 1.0) c = 1.0;
                out[0] = (float)(sum / c);
                g_done = 0;   // self-reset for next graph replay
            }
        }
    }
}

extern "C" void kernel_launch(void* const* d_in, const int* in_sizes, int n_in,
                              void* d_out, int out_size) {
    const float* seg_logits = (const float*)d_in[0];
    // d_in[1] = coord, unused
    const void* labels = d_in[2];
    const void* ref    = d_in[3];
    float* out = (float*)d_out;

    cudaFuncSetAttribute(lac_pass2, cudaFuncAttributeMaxDynamicSharedMemorySize,
                         SMEM_BYTES);

    const int TPB1 = 256;
    const int blocks1 = (N_POINTS + TPB1 - 1) / TPB1;   // 1024

    lac_pass1<<<blocks1, TPB1>>>(seg_logits, labels, ref);
    lac_pass2<<<GRID2, TPB2, SMEM_BYTES>>>(ref, out);
}

// round 8
// speedup vs baseline: 1.0894x; 1.0894x over previous
#include <cuda_runtime.h>
#include <cuda_bf16.h>
#include <cuda_fp16.h>

#define N_POINTS    262144
#define NUM_CLASSES 20
#define K_NEIGHBORS 16
#define FULLMASK    0xffffffffu

// packed labels: 5 bits each, 6 per uint32
#define NWORDS      43691            // ceil(262144 / 6)
#define NWORDS_PAD  43692            // multiple of 4 for uint4 copies
#define SMEM_BYTES  (NWORDS_PAD * 4) // 174768 B

#define GRID2       152
#define TPB2        1024
#define N_TASKS     (N_POINTS * 4)   // (point, quarter) tasks, 4 neighbors each

// probs as fp16: 3 transposed uint4 planes (8 halves = 8 classes per plane; 20..23 zero)
__device__ uint4 g_probsh[3 * N_POINTS];
__device__ unsigned g_packed[NWORDS_PAD];
__device__ double g_sum;
__device__ unsigned long long g_count;
__device__ unsigned int g_done;

// ---------------------------------------------------------------------------
// Index-dtype detection (values lie in [0,N); int32 read as int64 -> OOB).
// ---------------------------------------------------------------------------
__device__ __forceinline__ bool detect_is64(const void* __restrict__ ref_raw) {
    __shared__ int s_is64;
    if (threadIdx.x < 32) {
        const long long* p = (const long long*)ref_raw;
        long long a = p[threadIdx.x];
        long long b = p[threadIdx.x + 32];
        int bad = (a < 0 || a >= (long long)N_POINTS ||
                   b < 0 || b >= (long long)N_POINTS) ? 1 : 0;
        unsigned m = __ballot_sync(FULLMASK, bad);
        if (threadIdx.x == 0) s_is64 = (m == 0u);
    }
    __syncthreads();
    return s_is64 != 0;
}

// label extract from packed table: q = i/6 via reciprocal, r = i%6
__device__ __forceinline__ int lab_extract(const unsigned* __restrict__ tab, int i) {
    unsigned q = __umulhi((unsigned)i, 715827883u);   // floor(i/6) exact for i<2^18
    unsigned r = (unsigned)i - q * 6u;
    return (int)((tab[q] >> (r * 5u)) & 31u);
}

// squared-distance partial over one half2 pair (fp16 storage, fp32 math)
__device__ __forceinline__ float comp8(unsigned ua, unsigned ub, float d) {
    float2 fa = __half22float2(*(const __half2*)&ua);
    float2 fb = __half22float2(*(const __half2*)&ub);
    float d0 = fa.x - fb.x;
    float d1 = fa.y - fb.y;
    d = fmaf(d0, d0, d);
    return fmaf(d1, d1, d);
}

// ---------------------------------------------------------------------------
// Pass 1: zero accumulators, pack labels (5-bit), row softmax -> fp16 planes.
// ---------------------------------------------------------------------------
__global__ void lac_pass1(const float* __restrict__ logits,
                          const void* __restrict__ labels_raw,
                          const void* __restrict__ ref_raw) {
    const bool is64 = detect_is64(ref_raw);
    int i = blockIdx.x * blockDim.x + threadIdx.x;
    if (blockIdx.x == 0 && threadIdx.x == 0) { g_sum = 0.0; g_count = 0ULL; }

    if (i < NWORDS_PAD) {
        unsigned w = 0;
#pragma unroll
        for (int t = 0; t < 6; t++) {
            int p = i * 6 + t;
            int lbl = 31;   // invalid sentinel
            if (p < N_POINTS) {
                long long v = is64 ? ((const long long*)labels_raw)[p]
                                   : (long long)((const int*)labels_raw)[p];
                lbl = (int)v & 31;   // -1 -> 31 (invalid); 0..19 preserved
            }
            w |= (unsigned)lbl << (t * 5);
        }
        g_packed[i] = w;
    }

    if (i >= N_POINTS) return;

    const float4* in = (const float4*)logits + (long long)i * 5;
    float4 v[5];
#pragma unroll
    for (int j = 0; j < 5; j++) v[j] = in[j];
    float* f = (float*)v;

    float m = f[0];
#pragma unroll
    for (int j = 1; j < NUM_CLASSES; j++) m = fmaxf(m, f[j]);
    float s = 0.f;
#pragma unroll
    for (int j = 0; j < NUM_CLASSES; j++) { float e = __expf(f[j] - m); f[j] = e; s += e; }
    float inv = __frcp_rn(s);
#pragma unroll
    for (int j = 0; j < NUM_CLASSES; j++) f[j] *= inv;

    // pack to 10 half2 + 2 zero half2, store as 3 uint4 planes (transposed)
    unsigned h[12];
#pragma unroll
    for (int c = 0; c < 10; c++) {
        __half2 hh = __floats2half2_rn(f[2 * c], f[2 * c + 1]);
        h[c] = *(unsigned*)&hh;
    }
    h[10] = 0u; h[11] = 0u;
#pragma unroll
    for (int j = 0; j < 3; j++) {
        uint4 P;
        P.x = h[j * 4 + 0]; P.y = h[j * 4 + 1];
        P.z = h[j * 4 + 2]; P.w = h[j * 4 + 3];
        g_probsh[j * N_POINTS + i] = P;
    }
}

// ---------------------------------------------------------------------------
// Pass 2: persistent blocks; smem label table; (point,quarter) tasks;
// ffs-driven matched-gather loop over fp16 planes; block reduce; finalize.
// ---------------------------------------------------------------------------
__global__ void __launch_bounds__(TPB2, 1)
lac_pass2(const void* __restrict__ ref_raw, float* __restrict__ out) {
    extern __shared__ unsigned s_lab[];
    const bool is64 = detect_is64(ref_raw);

    {
        const uint4* src = (const uint4*)g_packed;
        uint4* dst = (uint4*)s_lab;
        for (int t = threadIdx.x; t < NWORDS_PAD / 4; t += blockDim.x)
            dst[t] = src[t];
    }
    __syncthreads();

    float acc = 0.f;
    int   cnt = 0;

    const int stride = GRID2 * TPB2;
    for (int task = blockIdx.x * TPB2 + threadIdx.x; task < N_TASKS; task += stride) {
        int i = task >> 2;          // point
        int q = task & 3;           // which 4-neighbor quarter

        // 4 neighbor indices, coalesced (sibling lanes contiguous)
        int idxv[4];
        if (is64) {
            const int4* base = (const int4*)((const char*)ref_raw +
                                (size_t)i * 128 + (size_t)q * 32);
            int4 v0 = base[0];
            int4 v1 = base[1];
            idxv[0] = v0.x; idxv[1] = v0.z;   // low words; -1 preserved
            idxv[2] = v1.x; idxv[3] = v1.z;
        } else {
            const int4* base = (const int4*)((const char*)ref_raw +
                                (size_t)i * 64 + (size_t)q * 16);
            int4 v0 = base[0];
            idxv[0] = v0.x; idxv[1] = v0.y; idxv[2] = v0.z; idxv[3] = v0.w;
        }

        int myl = lab_extract(s_lab, i);   // siblings broadcast

        // match mask from LDS labels
        unsigned mask = 0;
#pragma unroll
        for (int k = 0; k < 4; k++) {
            int safe = max(idxv[k], 0);
            int nl = lab_extract(s_lab, safe);
            if (idxv[k] >= 0 && nl == myl && myl != 31) mask |= 1u << k;
        }

        if (mask) {
            // self probs: 3 coalesced uint4 loads (siblings share lines)
            uint4 sp[3];
#pragma unroll
            for (int j = 0; j < 3; j++) sp[j] = g_probsh[j * N_POINTS + i];

            // iterate only over actual matches
            do {
                int k = __ffs(mask) - 1;
                mask &= mask - 1;
                int idx = idxv[k];
                float d = 0.f;
#pragma unroll
                for (int j = 0; j < 3; j++) {
                    uint4 qq = g_probsh[j * N_POINTS + idx];
                    d = comp8(sp[j].x, qq.x, d);
                    d = comp8(sp[j].y, qq.y, d);
                    d = comp8(sp[j].z, qq.z, d);
                    d = comp8(sp[j].w, qq.w, d);
                }
                acc += d;
                cnt++;
            } while (mask);
        }
    }

    // block reduction (32 warps) -> one atomic per block -> last-block finalize
#pragma unroll
    for (int o = 16; o > 0; o >>= 1) {
        acc += __shfl_down_sync(FULLMASK, acc, o);
        cnt += __shfl_down_sync(FULLMASK, cnt, o);
    }
    __shared__ float ssum[32];
    __shared__ int   scnt[32];
    int lane = threadIdx.x & 31;
    int w    = threadIdx.x >> 5;
    if (lane == 0) { ssum[w] = acc; scnt[w] = cnt; }
    __syncthreads();
    if (w == 0) {
        acc = ssum[lane];
        cnt = scnt[lane];
#pragma unroll
        for (int o = 16; o > 0; o >>= 1) {
            acc += __shfl_down_sync(FULLMASK, acc, o);
            cnt += __shfl_down_sync(FULLMASK, cnt, o);
        }
        if (lane == 0) {
            atomicAdd(&g_sum, (double)acc);
            atomicAdd(&g_count, (unsigned long long)cnt);
            __threadfence();
            unsigned int done = atomicAdd(&g_done, 1u);
            if (done == gridDim.x - 1) {
                double sum = *(volatile double*)&g_sum;
                double c   = (double)*(volatile unsigned long long*)&g_count;
                if (c < 1.0) c = 1.0;
                out[0] = (float)(sum / c);
                g_done = 0;   // self-reset for next graph replay
            }
        }
    }
}

extern "C" void kernel_launch(void* const* d_in, const int* in_sizes, int n_in,
                              void* d_out, int out_size) {
    const float* seg_logits = (const float*)d_in[0];
    // d_in[1] = coord, unused
    const void* labels = d_in[2];
    const void* ref    = d_in[3];
    float* out = (float*)d_out;

    cudaFuncSetAttribute(lac_pass2, cudaFuncAttributeMaxDynamicSharedMemorySize,
                         SMEM_BYTES);

    const int TPB1 = 256;
    const int blocks1 = (N_POINTS + TPB1 - 1) / TPB1;   // 1024

    lac_pass1<<<blocks1, TPB1>>>(seg_logits, labels, ref);
    lac_pass2<<<GRID2, TPB2, SMEM_BYTES>>>(ref, out);
}